// round 11
// baseline (speedup 1.0000x reference)
#include <cuda_runtime.h>
#include <cuda_fp16.h>
#include <cstdint>

#define D_DIM 1024
#define H_DIM 512

#define BM 128
#define BN 256
#define BK 32
#define STAGES 3
#define THREADS 256
#define NCH (D_DIM / BK)   // 32 k-chunks

// A stage: 128 rows x 36 floats (BK+4 pad) = 18432 B
#define SA_STRIDE 36
#define A_BYTES (BM * SA_STRIDE * 4)
// B stage: 256 n-rows x 40 halves (BK+8 pad) = 20480 B
#define SB_STRIDE 40
#define B_BYTES (BN * SB_STRIDE * 2)
#define STAGE_BYTES (A_BYTES + B_BYTES)          // 38912
#define EPI_BYTES ((H_DIM + H_DIM * 2) * 4)      // 6144: b1 + W2
#define SMEM_BYTES (STAGES * STAGE_BYTES + EPI_BYTES)   // 122880

__device__ __half g_W1Th[H_DIM * D_DIM];   // W1^T in fp16, [H][D] (k-contig)

__device__ __forceinline__ unsigned h2_as_u32(__half2 h) {
    __half2_raw r = *reinterpret_cast<__half2_raw*>(&h);
    return (unsigned)r.x | ((unsigned)r.y << 16);
}

__device__ __forceinline__ unsigned pack_h2(float lo, float hi) {
    return h2_as_u32(__floats2half2_rn(lo, hi));
}

__device__ __forceinline__ void mma_f16(float* d, const unsigned* a,
                                        const unsigned* b, const float* c) {
    asm volatile(
        "mma.sync.aligned.m16n8k16.row.col.f32.f16.f16.f32 "
        "{%0,%1,%2,%3}, {%4,%5,%6,%7}, {%8,%9}, {%10,%11,%12,%13};\n"
        : "=f"(d[0]), "=f"(d[1]), "=f"(d[2]), "=f"(d[3])
        : "r"(a[0]), "r"(a[1]), "r"(a[2]), "r"(a[3]),
          "r"(b[0]), "r"(b[1]),
          "f"(c[0]), "f"(c[1]), "f"(c[2]), "f"(c[3]));
}

__device__ __forceinline__ void cp_async16(void* smem_dst, const void* gsrc) {
    uint32_t d = (uint32_t)__cvta_generic_to_shared(smem_dst);
    asm volatile("cp.async.cg.shared.global [%0], [%1], 16;" :: "r"(d),
                 "l"(gsrc) : "memory");
}

// ---- prep: W1 [D][H] fp32 -> W1^T [H][D] fp16 ----
__global__ void transpose_w1_kernel(const float* __restrict__ W1) {
    __shared__ float tile[32][33];
    int k0 = blockIdx.x * 32, n0 = blockIdx.y * 32;
    int tx = threadIdx.x, ty = threadIdx.y;   // (32, 8)
#pragma unroll
    for (int i = 0; i < 32; i += 8)
        tile[ty + i][tx] = W1[(size_t)(k0 + ty + i) * H_DIM + n0 + tx];
    __syncthreads();
#pragma unroll
    for (int i = 0; i < 32; i += 8)
        g_W1Th[(size_t)(n0 + ty + i) * D_DIM + k0 + tx] =
            __float2half_rn(tile[tx][ty + i]);
}

__global__ void init_patch_kernel(const float* __restrict__ b2,
                                  float* __restrict__ patch_logits, int total) {
    int i = blockIdx.x * blockDim.x + threadIdx.x;
    if (i < total) patch_logits[i] = b2[i & 1];
}

// ---- fused pipelined fp16 GEMM: patch_logits += relu((att*X)@W1 + b1) @ W2 ----
__global__ __launch_bounds__(THREADS, 1)
void gemm_fused_kernel(const float* __restrict__ features,
                       const float* __restrict__ attention,
                       const float* __restrict__ b1,
                       const float* __restrict__ W2,
                       float* __restrict__ patch_logits) {
    extern __shared__ char smem[];
    float* sEpi = (float*)(smem + STAGES * STAGE_BYTES);

    const int tid = threadIdx.x;
    const int hblk = blockIdx.x;            // 0..1 (fast dim: L2 reuse of A)
    const int row0 = blockIdx.y * BM;
    const int h0 = hblk * BN;

    const int wid = tid >> 5;
    const int lane = tid & 31;
    const int gid = lane >> 2;              // 0..7
    const int tig = lane & 3;               // 0..3
    const int warp_m = (wid & 1) * 64;      // 0,64
    const int warp_n = (wid >> 1) * 64;     // 0,64,128,192

    // epilogue constants -> smem (visible after first in-loop barrier)
    for (int i = tid; i < H_DIM; i += THREADS) sEpi[i] = b1[i];
    for (int i = tid; i < H_DIM * 2; i += THREADS) sEpi[H_DIM + i] = W2[i];

    // per-thread attention for the 8 A-fragment rows
    float attv[4][2];
#pragma unroll
    for (int mt = 0; mt < 4; mt++) {
        int r = row0 + warp_m + mt * 16 + gid;
        attv[mt][0] = __ldg(&attention[r]);
        attv[mt][1] = __ldg(&attention[r + 8]);
    }

    auto fill = [&](int slot, int kchunk) {
        const int k0 = kchunk * BK;
        float* sA = (float*)(smem + slot * STAGE_BYTES);
        __half* sB = (__half*)(smem + slot * STAGE_BYTES + A_BYTES);
#pragma unroll
        for (int i = 0; i < 4; i++) {
            int idx = i * THREADS + tid;    // 0..1023
            int r = idx >> 3;               // 0..127
            int c = idx & 7;                // 8 x 16B per row
            cp_async16(&sA[r * SA_STRIDE + c * 4],
                       &features[(size_t)(row0 + r) * D_DIM + k0 + c * 4]);
        }
#pragma unroll
        for (int i = 0; i < 4; i++) {
            int idx = i * THREADS + tid;    // 0..1023
            int n = idx >> 2;               // 0..255
            int c = idx & 3;                // 4 x 16B per row (32 fp16)
            cp_async16(&sB[n * SB_STRIDE + c * 8],
                       &g_W1Th[(size_t)(h0 + n) * D_DIM + k0 + c * 8]);
        }
        asm volatile("cp.async.commit_group;" ::: "memory");
    };

    float acc[4][8][4];
#pragma unroll
    for (int mt = 0; mt < 4; mt++)
#pragma unroll
        for (int nt = 0; nt < 8; nt++)
#pragma unroll
            for (int j = 0; j < 4; j++) acc[mt][nt][j] = 0.0f;

    fill(0, 0);
    fill(1, 1);

    for (int ch = 0; ch < NCH; ch++) {
        if (ch == NCH - 1)
            asm volatile("cp.async.wait_group 0;" ::: "memory");
        else
            asm volatile("cp.async.wait_group 1;" ::: "memory");
        __syncthreads();
        if (ch + 2 < NCH) fill((ch + 2) % STAGES, ch + 2);

        const float* sA = (const float*)(smem + (ch % STAGES) * STAGE_BYTES);
        const __half* sB =
            (const __half*)(smem + (ch % STAGES) * STAGE_BYTES + A_BYTES);

#pragma unroll
        for (int ks = 0; ks < 2; ks++) {    // two k16 steps per BK=32
            const int kb = ks * 16;
            unsigned afr[4][4];
#pragma unroll
            for (int mt = 0; mt < 4; mt++) {
                int r = warp_m + mt * 16 + gid;
                float2 f0 = *reinterpret_cast<const float2*>(
                    &sA[r * SA_STRIDE + kb + 2 * tig]);
                float2 f1 = *reinterpret_cast<const float2*>(
                    &sA[(r + 8) * SA_STRIDE + kb + 2 * tig]);
                float2 f2 = *reinterpret_cast<const float2*>(
                    &sA[r * SA_STRIDE + kb + 2 * tig + 8]);
                float2 f3 = *reinterpret_cast<const float2*>(
                    &sA[(r + 8) * SA_STRIDE + kb + 2 * tig + 8]);
                float a0 = attv[mt][0], a1 = attv[mt][1];
                afr[mt][0] = pack_h2(f0.x * a0, f0.y * a0);
                afr[mt][1] = pack_h2(f1.x * a1, f1.y * a1);
                afr[mt][2] = pack_h2(f2.x * a0, f2.y * a0);
                afr[mt][3] = pack_h2(f3.x * a1, f3.y * a1);
            }
            unsigned bfr[8][2];
#pragma unroll
            for (int nt = 0; nt < 8; nt++) {
                int n = warp_n + nt * 8 + gid;
                bfr[nt][0] = *reinterpret_cast<const unsigned*>(
                    &sB[n * SB_STRIDE + kb + 2 * tig]);
                bfr[nt][1] = *reinterpret_cast<const unsigned*>(
                    &sB[n * SB_STRIDE + kb + 2 * tig + 8]);
            }
#pragma unroll
            for (int mt = 0; mt < 4; mt++)
#pragma unroll
                for (int nt = 0; nt < 8; nt++)
                    mma_f16(acc[mt][nt], afr[mt], bfr[nt], acc[mt][nt]);
        }
    }

    // ---- epilogue: +b1, ReLU, fold W2; quad-reduce; atomic accumulate ----
    const float* b1s = sEpi;
    const float* w2s = sEpi + H_DIM;
#pragma unroll
    for (int mt = 0; mt < 4; mt++) {
#pragma unroll
        for (int half = 0; half < 2; half++) {
            int r = row0 + warp_m + mt * 16 + gid + half * 8;
            float pl0 = 0.0f, pl1 = 0.0f;
#pragma unroll
            for (int nt = 0; nt < 8; nt++) {
#pragma unroll
                for (int j = 0; j < 2; j++) {
                    int col = h0 + warp_n + nt * 8 + 2 * tig + j;
                    float v = acc[mt][nt][half * 2 + j] + b1s[col];
                    v = fmaxf(v, 0.0f);
                    pl0 = fmaf(v, w2s[col * 2 + 0], pl0);
                    pl1 = fmaf(v, w2s[col * 2 + 1], pl1);
                }
            }
            pl0 += __shfl_xor_sync(0xFFFFFFFFu, pl0, 1);
            pl1 += __shfl_xor_sync(0xFFFFFFFFu, pl1, 1);
            pl0 += __shfl_xor_sync(0xFFFFFFFFu, pl0, 2);
            pl1 += __shfl_xor_sync(0xFFFFFFFFu, pl1, 2);
            if (tig == 0) {
                atomicAdd(&patch_logits[(size_t)r * 2 + 0], pl0);
                atomicAdd(&patch_logits[(size_t)r * 2 + 1], pl1);
            }
        }
    }
}

// ---- per-bag ragged segment sum ----
__global__ void bag_sum_kernel(const float* __restrict__ patch_logits,
                               const int* __restrict__ bag_sizes,
                               float* __restrict__ logits) {
    int b = blockIdx.x;
    int start = 0;
    for (int i = 0; i < b; i++) start += bag_sizes[i];
    int size = bag_sizes[b];

    float s0 = 0.0f, s1 = 0.0f;
    const float2* pl = reinterpret_cast<const float2*>(patch_logits);
    for (int i = threadIdx.x; i < size; i += blockDim.x) {
        float2 v = pl[start + i];
        s0 += v.x;
        s1 += v.y;
    }
#pragma unroll
    for (int off = 16; off > 0; off >>= 1) {
        s0 += __shfl_down_sync(0xFFFFFFFFu, s0, off);
        s1 += __shfl_down_sync(0xFFFFFFFFu, s1, off);
    }
    __shared__ float r0[8], r1[8];
    int w = threadIdx.x >> 5;
    if ((threadIdx.x & 31) == 0) { r0[w] = s0; r1[w] = s1; }
    __syncthreads();
    if (threadIdx.x == 0) {
        float t0 = 0.0f, t1 = 0.0f;
        int nw = blockDim.x >> 5;
        for (int i = 0; i < nw; i++) { t0 += r0[i]; t1 += r1[i]; }
        logits[b * 2 + 0] = t0;
        logits[b * 2 + 1] = t1;
    }
}

// ---- launch ----
extern "C" void kernel_launch(void* const* d_in, const int* in_sizes, int n_in,
                              void* d_out, int out_size) {
    const float* features  = (const float*)d_in[0];  // [N, D]
    const float* attention = (const float*)d_in[1];  // [N, 1]
    const int*   bag_sizes = (const int*)d_in[2];    // [B]
    const float* W1        = (const float*)d_in[3];  // [D, H]
    const float* b1        = (const float*)d_in[4];  // [H]
    const float* W2        = (const float*)d_in[5];  // [H, C]
    const float* b2        = (const float*)d_in[6];  // [C]

    const int N = in_sizes[1];
    const int B = in_sizes[2];

    float* logits = (float*)d_out;                  // [B, 2]
    float* patch_logits = logits + (size_t)B * 2;   // [N, 2]

    cudaFuncSetAttribute(gemm_fused_kernel,
                         cudaFuncAttributeMaxDynamicSharedMemorySize,
                         SMEM_BYTES);

    // 1) prep: W1 -> fp16 transposed scratch; patch_logits = b2 broadcast
    transpose_w1_kernel<<<dim3(D_DIM / 32, H_DIM / 32), dim3(32, 8)>>>(W1);
    init_patch_kernel<<<(N * 2 + 255) / 256, 256>>>(b2, patch_logits, N * 2);

    // 2) fused pipelined fp16 GEMM
    dim3 grid(H_DIM / BN, N / BM);
    gemm_fused_kernel<<<grid, THREADS, SMEM_BYTES>>>(features, attention, b1,
                                                     W2, patch_logits);

    // 3) ragged per-bag segment sum
    bag_sum_kernel<<<B, 256>>>(patch_logits, bag_sizes, logits);
}

// round 14
// speedup vs baseline: 1.3891x; 1.3891x over previous
#include <cuda_runtime.h>
#include <cstdint>

#define D_DIM 1024
#define H_DIM 512

#define BM 128
#define BN 256
#define BK 32
#define STAGES 3
#define THREADS 256
#define NCH (D_DIM / BK)   // 32 k-chunks

#define SA_STRIDE 36       // floats per A row (BK + 4 pad)
#define SB_STRIDE 264      // floats per B row (BN + 8 pad)
#define A_STAGE_FLOATS (BM * SA_STRIDE)   // 4608
#define B_STAGE_FLOATS (BK * SB_STRIDE)   // 8448
#define STAGE_FLOATS (A_STAGE_FLOATS + B_STAGE_FLOATS)
#define EPI_FLOATS (H_DIM + H_DIM * 2)    // b1[512] + W2[1024]
#define SMEM_FLOATS (STAGES * STAGE_FLOATS + EPI_FLOATS)
#define SMEM_BYTES (SMEM_FLOATS * 4)      // 162816

__device__ float g_W1tf[D_DIM * H_DIM];   // W1 pre-rounded to tf32, [D][H]

__device__ __forceinline__ float to_tf32(float x) {
    float y;
    asm("cvt.rna.tf32.f32 %0, %1;" : "=f"(y) : "f"(x));
    return y;
}

__device__ __forceinline__ void mma_tf32(float* d, const unsigned* a,
                                         const unsigned* b, const float* c) {
    asm volatile(
        "mma.sync.aligned.m16n8k8.row.col.f32.tf32.tf32.f32 "
        "{%0,%1,%2,%3}, {%4,%5,%6,%7}, {%8,%9}, {%10,%11,%12,%13};\n"
        : "=f"(d[0]), "=f"(d[1]), "=f"(d[2]), "=f"(d[3])
        : "r"(a[0]), "r"(a[1]), "r"(a[2]), "r"(a[3]),
          "r"(b[0]), "r"(b[1]),
          "f"(c[0]), "f"(c[1]), "f"(c[2]), "f"(c[3]));
}

__device__ __forceinline__ void cp_async16(void* smem_dst, const void* gsrc) {
    uint32_t d = (uint32_t)__cvta_generic_to_shared(smem_dst);
    asm volatile("cp.async.cg.shared.global [%0], [%1], 16;" :: "r"(d),
                 "l"(gsrc) : "memory");
}

// ---- tiny prep kernels ----
__global__ void cvt_w1_kernel(const float* __restrict__ W1) {
    int i = blockIdx.x * blockDim.x + threadIdx.x;   // over float4s
    float4 f = reinterpret_cast<const float4*>(W1)[i];
    f.x = to_tf32(f.x); f.y = to_tf32(f.y);
    f.z = to_tf32(f.z); f.w = to_tf32(f.w);
    reinterpret_cast<float4*>(g_W1tf)[i] = f;
}

__global__ void init_patch_kernel(const float* __restrict__ b2,
                                  float* __restrict__ patch_logits, int total) {
    int i = blockIdx.x * blockDim.x + threadIdx.x;
    if (i < total) patch_logits[i] = b2[i & 1];
}

// ---- fused pipelined GEMM: patch_logits += relu(att*(X@W1) + b1) @ W2 ----
__global__ __launch_bounds__(THREADS, 1)
void gemm_fused_kernel(const float* __restrict__ features,
                       const float* __restrict__ attention,
                       const float* __restrict__ b1,
                       const float* __restrict__ W2,
                       float* __restrict__ patch_logits) {
    extern __shared__ float smem[];
    float* sEpi = smem + STAGES * STAGE_FLOATS;

    const int tid = threadIdx.x;
    const int hblk = blockIdx.x;            // 0..1 (fast dim: L2 reuse of A)
    const int row0 = blockIdx.y * BM;
    const int h0 = hblk * BN;

    const int wid = tid >> 5;
    const int lane = tid & 31;
    const int gid = lane >> 2;              // 0..7
    const int tig = lane & 3;               // 0..3
    const int warp_m = (wid & 1) * 64;      // 0,64
    const int warp_n = (wid >> 1) * 64;     // 0,64,128,192

    // epilogue constants -> smem (visible after first in-loop barrier)
    for (int i = tid; i < H_DIM; i += THREADS) sEpi[i] = b1[i];
    for (int i = tid; i < H_DIM * 2; i += THREADS) sEpi[H_DIM + i] = W2[i];

    // per-thread attention for the 8 epilogue rows
    float attv[4][2];
#pragma unroll
    for (int mt = 0; mt < 4; mt++) {
        int r = row0 + warp_m + mt * 16 + gid;
        attv[mt][0] = __ldg(&attention[r]);
        attv[mt][1] = __ldg(&attention[r + 8]);
    }

    // stage fill: A = raw features rows (fp32), B = pre-tf32 W1 rows
    auto fill = [&](int slot, int kchunk) {
        const int k0 = kchunk * BK;
        float* sA = smem + slot * STAGE_FLOATS;
        float* sB = sA + A_STAGE_FLOATS;
#pragma unroll
        for (int i = 0; i < 4; i++) {
            int idx = i * THREADS + tid;    // 0..1023
            int r = idx >> 3;               // 0..127
            int c = idx & 7;                // 8 x 16B per row
            cp_async16(&sA[r * SA_STRIDE + c * 4],
                       &features[(size_t)(row0 + r) * D_DIM + k0 + c * 4]);
        }
#pragma unroll
        for (int i = 0; i < 8; i++) {
            int idx = i * THREADS + tid;    // 0..2047
            int kr = idx >> 6;              // 0..31
            int c = idx & 63;               // 0..63
            cp_async16(&sB[kr * SB_STRIDE + c * 4],
                       &g_W1tf[(size_t)(k0 + kr) * H_DIM + h0 + c * 4]);
        }
        asm volatile("cp.async.commit_group;" ::: "memory");
    };

    float acc[4][8][4];
#pragma unroll
    for (int mt = 0; mt < 4; mt++)
#pragma unroll
        for (int nt = 0; nt < 8; nt++)
#pragma unroll
            for (int j = 0; j < 4; j++) acc[mt][nt][j] = 0.0f;

    fill(0, 0);
    fill(1, 1);

    for (int ch = 0; ch < NCH; ch++) {
        if (ch == NCH - 1)
            asm volatile("cp.async.wait_group 0;" ::: "memory");
        else
            asm volatile("cp.async.wait_group 1;" ::: "memory");
        __syncthreads();
        if (ch + 2 < NCH) fill((ch + 2) % STAGES, ch + 2);

        const float* sA = smem + (ch % STAGES) * STAGE_FLOATS;
        const float* sB = sA + A_STAGE_FLOATS;

#pragma unroll
        for (int kk = 0; kk < BK; kk += 8) {
            // A fragments: raw fp32 bits (HW truncates to tf32) — no cvt, no mul
            unsigned afr[4][4];
#pragma unroll
            for (int mt = 0; mt < 4; mt++) {
                int r = warp_m + mt * 16 + gid;
                afr[mt][0] = __float_as_uint(sA[r * SA_STRIDE + kk + tig]);
                afr[mt][1] = __float_as_uint(sA[(r + 8) * SA_STRIDE + kk + tig]);
                afr[mt][2] = __float_as_uint(sA[r * SA_STRIDE + kk + tig + 4]);
                afr[mt][3] = __float_as_uint(sA[(r + 8) * SA_STRIDE + kk + tig + 4]);
            }
            unsigned bfr[8][2];
#pragma unroll
            for (int nt = 0; nt < 8; nt++) {
                int col = warp_n + nt * 8 + gid;
                bfr[nt][0] = __float_as_uint(sB[(kk + tig) * SB_STRIDE + col]);
                bfr[nt][1] = __float_as_uint(sB[(kk + tig + 4) * SB_STRIDE + col]);
            }
#pragma unroll
            for (int mt = 0; mt < 4; mt++)
#pragma unroll
                for (int nt = 0; nt < 8; nt++)
                    mma_tf32(acc[mt][nt], afr[mt], bfr[nt], acc[mt][nt]);
        }
    }

    // ---- epilogue: att*acc + b1, ReLU, fold W2; quad-reduce; atomics ----
    const float* b1s = sEpi;
    const float* w2s = sEpi + H_DIM;
#pragma unroll
    for (int mt = 0; mt < 4; mt++) {
#pragma unroll
        for (int half = 0; half < 2; half++) {
            int r = row0 + warp_m + mt * 16 + gid + half * 8;
            float att = attv[mt][half];
            float pl0 = 0.0f, pl1 = 0.0f;
#pragma unroll
            for (int nt = 0; nt < 8; nt++) {
#pragma unroll
                for (int j = 0; j < 2; j++) {
                    int col = h0 + warp_n + nt * 8 + 2 * tig + j;
                    float v = fmaf(att, acc[mt][nt][half * 2 + j], b1s[col]);
                    v = fmaxf(v, 0.0f);
                    pl0 = fmaf(v, w2s[col * 2 + 0], pl0);
                    pl1 = fmaf(v, w2s[col * 2 + 1], pl1);
                }
            }
            pl0 += __shfl_xor_sync(0xFFFFFFFFu, pl0, 1);
            pl1 += __shfl_xor_sync(0xFFFFFFFFu, pl1, 1);
            pl0 += __shfl_xor_sync(0xFFFFFFFFu, pl0, 2);
            pl1 += __shfl_xor_sync(0xFFFFFFFFu, pl1, 2);
            if (tig == 0) {
                atomicAdd(&patch_logits[(size_t)r * 2 + 0], pl0);
                atomicAdd(&patch_logits[(size_t)r * 2 + 1], pl1);
            }
        }
    }
}

// ---- per-bag ragged segment sum ----
__global__ void bag_sum_kernel(const float* __restrict__ patch_logits,
                               const int* __restrict__ bag_sizes,
                               float* __restrict__ logits) {
    int b = blockIdx.x;
    int start = 0;
    for (int i = 0; i < b; i++) start += bag_sizes[i];
    int size = bag_sizes[b];

    float s0 = 0.0f, s1 = 0.0f;
    const float2* pl = reinterpret_cast<const float2*>(patch_logits);
    for (int i = threadIdx.x; i < size; i += blockDim.x) {
        float2 v = pl[start + i];
        s0 += v.x;
        s1 += v.y;
    }
#pragma unroll
    for (int off = 16; off > 0; off >>= 1) {
        s0 += __shfl_down_sync(0xFFFFFFFFu, s0, off);
        s1 += __shfl_down_sync(0xFFFFFFFFu, s1, off);
    }
    __shared__ float r0[8], r1[8];
    int w = threadIdx.x >> 5;
    if ((threadIdx.x & 31) == 0) { r0[w] = s0; r1[w] = s1; }
    __syncthreads();
    if (threadIdx.x == 0) {
        float t0 = 0.0f, t1 = 0.0f;
        int nw = blockDim.x >> 5;
        for (int i = 0; i < nw; i++) { t0 += r0[i]; t1 += r1[i]; }
        logits[b * 2 + 0] = t0;
        logits[b * 2 + 1] = t1;
    }
}

// ---- launch ----
extern "C" void kernel_launch(void* const* d_in, const int* in_sizes, int n_in,
                              void* d_out, int out_size) {
    const float* features  = (const float*)d_in[0];  // [N, D]
    const float* attention = (const float*)d_in[1];  // [N, 1]
    const int*   bag_sizes = (const int*)d_in[2];    // [B]
    const float* W1        = (const float*)d_in[3];  // [D, H]
    const float* b1        = (const float*)d_in[4];  // [H]
    const float* W2        = (const float*)d_in[5];  // [H, C]
    const float* b2        = (const float*)d_in[6];  // [C]

    const int N = in_sizes[1];
    const int B = in_sizes[2];

    float* logits = (float*)d_out;                  // [B, 2]
    float* patch_logits = logits + (size_t)B * 2;   // [N, 2]

    cudaFuncSetAttribute(gemm_fused_kernel,
                         cudaFuncAttributeMaxDynamicSharedMemorySize,
                         SMEM_BYTES);

    // 1) prep: W1 -> tf32 scratch; patch_logits = b2 broadcast
    cvt_w1_kernel<<<(D_DIM * H_DIM / 4) / 256, 256>>>(W1);
    init_patch_kernel<<<(N * 2 + 255) / 256, 256>>>(b2, patch_logits, N * 2);

    // 2) fused pipelined GEMM
    dim3 grid(H_DIM / BN, N / BM);
    gemm_fused_kernel<<<grid, THREADS, SMEM_BYTES>>>(features, attention, b1,
                                                     W2, patch_logits);

    // 3) ragged per-bag segment sum
    bag_sum_kernel<<<B, 256>>>(patch_logits, bag_sizes, logits);
}

// round 15
// speedup vs baseline: 1.4155x; 1.0190x over previous
#include <cuda_runtime.h>
#include <cstdint>

#define D_DIM 1024
#define H_DIM 512

#define BM 128
#define BN 128
#define BK 32
#define STAGES 3
#define THREADS 256
#define NCH (D_DIM / BK)   // 32 k-chunks

#define SA_STRIDE 36       // floats per A row (BK + 4 pad) -> banks 4*gid+tig distinct
#define SB_STRIDE 136      // floats per B row (BN + 8 pad) -> banks 8*tig+gid distinct
#define A_STAGE_FLOATS (BM * SA_STRIDE)   // 4608
#define B_STAGE_FLOATS (BK * SB_STRIDE)   // 4352
#define STAGE_FLOATS (A_STAGE_FLOATS + B_STAGE_FLOATS)   // 8960
#define EPI_FLOATS (H_DIM + H_DIM * 2)    // b1[512] + W2[1024]
#define SMEM_FLOATS (STAGES * STAGE_FLOATS + EPI_FLOATS)
#define SMEM_BYTES (SMEM_FLOATS * 4)      // 113664 -> 2 CTAs/SM

__device__ float g_W1tf[D_DIM * H_DIM];   // W1 pre-rounded to tf32, [D][H]

__device__ __forceinline__ float to_tf32(float x) {
    float y;
    asm("cvt.rna.tf32.f32 %0, %1;" : "=f"(y) : "f"(x));
    return y;
}

__device__ __forceinline__ void mma_tf32(float* d, const unsigned* a,
                                         const unsigned* b, const float* c) {
    asm volatile(
        "mma.sync.aligned.m16n8k8.row.col.f32.tf32.tf32.f32 "
        "{%0,%1,%2,%3}, {%4,%5,%6,%7}, {%8,%9}, {%10,%11,%12,%13};\n"
        : "=f"(d[0]), "=f"(d[1]), "=f"(d[2]), "=f"(d[3])
        : "r"(a[0]), "r"(a[1]), "r"(a[2]), "r"(a[3]),
          "r"(b[0]), "r"(b[1]),
          "f"(c[0]), "f"(c[1]), "f"(c[2]), "f"(c[3]));
}

__device__ __forceinline__ void cp_async16(void* smem_dst, const void* gsrc) {
    uint32_t d = (uint32_t)__cvta_generic_to_shared(smem_dst);
    asm volatile("cp.async.cg.shared.global [%0], [%1], 16;" :: "r"(d),
                 "l"(gsrc) : "memory");
}

// ---- tiny prep kernels ----
__global__ void cvt_w1_kernel(const float* __restrict__ W1) {
    int i = blockIdx.x * blockDim.x + threadIdx.x;   // over float4s
    float4 f = reinterpret_cast<const float4*>(W1)[i];
    f.x = to_tf32(f.x); f.y = to_tf32(f.y);
    f.z = to_tf32(f.z); f.w = to_tf32(f.w);
    reinterpret_cast<float4*>(g_W1tf)[i] = f;
}

__global__ void init_patch_kernel(const float* __restrict__ b2,
                                  float* __restrict__ patch_logits, int total) {
    int i = blockIdx.x * blockDim.x + threadIdx.x;
    if (i < total) patch_logits[i] = b2[i & 1];
}

// ---- fused pipelined GEMM: patch_logits += relu(att*(X@W1) + b1) @ W2 ----
__global__ __launch_bounds__(THREADS, 2)
void gemm_fused_kernel(const float* __restrict__ features,
                       const float* __restrict__ attention,
                       const float* __restrict__ b1,
                       const float* __restrict__ W2,
                       float* __restrict__ patch_logits) {
    extern __shared__ float smem[];
    float* sEpi = smem + STAGES * STAGE_FLOATS;

    const int tid = threadIdx.x;
    const int hblk = blockIdx.x;            // 0..3 (fast dim: L2 reuse of A)
    const int row0 = blockIdx.y * BM;
    const int h0 = hblk * BN;

    const int wid = tid >> 5;
    const int lane = tid & 31;
    const int gid = lane >> 2;              // 0..7
    const int tig = lane & 3;               // 0..3
    const int warp_m = (wid & 1) * 64;      // 0,64
    const int warp_n = (wid >> 1) * 32;     // 0,32,64,96

    // epilogue constants -> smem (visible after first in-loop barrier)
    for (int i = tid; i < H_DIM; i += THREADS) sEpi[i] = b1[i];
    for (int i = tid; i < H_DIM * 2; i += THREADS) sEpi[H_DIM + i] = W2[i];

    // per-thread attention for the 8 epilogue rows
    float attv[4][2];
#pragma unroll
    for (int mt = 0; mt < 4; mt++) {
        int r = row0 + warp_m + mt * 16 + gid;
        attv[mt][0] = __ldg(&attention[r]);
        attv[mt][1] = __ldg(&attention[r + 8]);
    }

    // stage fill: A = raw features rows (fp32), B = pre-tf32 W1 rows
    auto fill = [&](int slot, int kchunk) {
        const int k0 = kchunk * BK;
        float* sA = smem + slot * STAGE_FLOATS;
        float* sB = sA + A_STAGE_FLOATS;
#pragma unroll
        for (int i = 0; i < 4; i++) {
            int idx = i * THREADS + tid;    // 0..1023
            int r = idx >> 3;               // 0..127
            int c = idx & 7;                // 8 x 16B per row
            cp_async16(&sA[r * SA_STRIDE + c * 4],
                       &features[(size_t)(row0 + r) * D_DIM + k0 + c * 4]);
        }
#pragma unroll
        for (int i = 0; i < 4; i++) {
            int idx = i * THREADS + tid;    // 0..1023
            int kr = idx >> 5;              // 0..31
            int c = idx & 31;               // 32 x 16B per row (128 floats)
            cp_async16(&sB[kr * SB_STRIDE + c * 4],
                       &g_W1tf[(size_t)(k0 + kr) * H_DIM + h0 + c * 4]);
        }
        asm volatile("cp.async.commit_group;" ::: "memory");
    };

    float acc[4][4][4];
#pragma unroll
    for (int mt = 0; mt < 4; mt++)
#pragma unroll
        for (int nt = 0; nt < 4; nt++)
#pragma unroll
            for (int j = 0; j < 4; j++) acc[mt][nt][j] = 0.0f;

    fill(0, 0);
    fill(1, 1);

    for (int ch = 0; ch < NCH; ch++) {
        if (ch == NCH - 1)
            asm volatile("cp.async.wait_group 0;" ::: "memory");
        else
            asm volatile("cp.async.wait_group 1;" ::: "memory");
        __syncthreads();
        if (ch + 2 < NCH) fill((ch + 2) % STAGES, ch + 2);

        const float* sA = smem + (ch % STAGES) * STAGE_FLOATS;
        const float* sB = sA + A_STAGE_FLOATS;

#pragma unroll
        for (int kk = 0; kk < BK; kk += 8) {
            // A fragments: raw fp32 bits (HW truncates to tf32)
            unsigned afr[4][4];
#pragma unroll
            for (int mt = 0; mt < 4; mt++) {
                int r = warp_m + mt * 16 + gid;
                afr[mt][0] = __float_as_uint(sA[r * SA_STRIDE + kk + tig]);
                afr[mt][1] = __float_as_uint(sA[(r + 8) * SA_STRIDE + kk + tig]);
                afr[mt][2] = __float_as_uint(sA[r * SA_STRIDE + kk + tig + 4]);
                afr[mt][3] = __float_as_uint(sA[(r + 8) * SA_STRIDE + kk + tig + 4]);
            }
            unsigned bfr[4][2];
#pragma unroll
            for (int nt = 0; nt < 4; nt++) {
                int col = warp_n + nt * 8 + gid;
                bfr[nt][0] = __float_as_uint(sB[(kk + tig) * SB_STRIDE + col]);
                bfr[nt][1] = __float_as_uint(sB[(kk + tig + 4) * SB_STRIDE + col]);
            }
#pragma unroll
            for (int mt = 0; mt < 4; mt++)
#pragma unroll
                for (int nt = 0; nt < 4; nt++)
                    mma_tf32(acc[mt][nt], afr[mt], bfr[nt], acc[mt][nt]);
        }
    }

    // ---- epilogue: att*acc + b1, ReLU, fold W2; quad-reduce; atomics ----
    const float* b1s = sEpi;
    const float* w2s = sEpi + H_DIM;
#pragma unroll
    for (int mt = 0; mt < 4; mt++) {
#pragma unroll
        for (int half = 0; half < 2; half++) {
            int r = row0 + warp_m + mt * 16 + gid + half * 8;
            float att = attv[mt][half];
            float pl0 = 0.0f, pl1 = 0.0f;
#pragma unroll
            for (int nt = 0; nt < 4; nt++) {
#pragma unroll
                for (int j = 0; j < 2; j++) {
                    int col = h0 + warp_n + nt * 8 + 2 * tig + j;
                    float v = fmaf(att, acc[mt][nt][half * 2 + j], b1s[col]);
                    v = fmaxf(v, 0.0f);
                    pl0 = fmaf(v, w2s[col * 2 + 0], pl0);
                    pl1 = fmaf(v, w2s[col * 2 + 1], pl1);
                }
            }
            pl0 += __shfl_xor_sync(0xFFFFFFFFu, pl0, 1);
            pl1 += __shfl_xor_sync(0xFFFFFFFFu, pl1, 1);
            pl0 += __shfl_xor_sync(0xFFFFFFFFu, pl0, 2);
            pl1 += __shfl_xor_sync(0xFFFFFFFFu, pl1, 2);
            if (tig == 0) {
                atomicAdd(&patch_logits[(size_t)r * 2 + 0], pl0);
                atomicAdd(&patch_logits[(size_t)r * 2 + 1], pl1);
            }
        }
    }
}

// ---- per-bag ragged segment sum ----
__global__ void bag_sum_kernel(const float* __restrict__ patch_logits,
                               const int* __restrict__ bag_sizes,
                               float* __restrict__ logits) {
    int b = blockIdx.x;
    int start = 0;
    for (int i = 0; i < b; i++) start += bag_sizes[i];
    int size = bag_sizes[b];

    float s0 = 0.0f, s1 = 0.0f;
    const float2* pl = reinterpret_cast<const float2*>(patch_logits);
    for (int i = threadIdx.x; i < size; i += blockDim.x) {
        float2 v = pl[start + i];
        s0 += v.x;
        s1 += v.y;
    }
#pragma unroll
    for (int off = 16; off > 0; off >>= 1) {
        s0 += __shfl_down_sync(0xFFFFFFFFu, s0, off);
        s1 += __shfl_down_sync(0xFFFFFFFFu, s1, off);
    }
    __shared__ float r0[8], r1[8];
    int w = threadIdx.x >> 5;
    if ((threadIdx.x & 31) == 0) { r0[w] = s0; r1[w] = s1; }
    __syncthreads();
    if (threadIdx.x == 0) {
        float t0 = 0.0f, t1 = 0.0f;
        int nw = blockDim.x >> 5;
        for (int i = 0; i < nw; i++) { t0 += r0[i]; t1 += r1[i]; }
        logits[b * 2 + 0] = t0;
        logits[b * 2 + 1] = t1;
    }
}

// ---- launch ----
extern "C" void kernel_launch(void* const* d_in, const int* in_sizes, int n_in,
                              void* d_out, int out_size) {
    const float* features  = (const float*)d_in[0];  // [N, D]
    const float* attention = (const float*)d_in[1];  // [N, 1]
    const int*   bag_sizes = (const int*)d_in[2];    // [B]
    const float* W1        = (const float*)d_in[3];  // [D, H]
    const float* b1        = (const float*)d_in[4];  // [H]
    const float* W2        = (const float*)d_in[5];  // [H, C]
    const float* b2        = (const float*)d_in[6];  // [C]

    const int N = in_sizes[1];
    const int B = in_sizes[2];

    float* logits = (float*)d_out;                  // [B, 2]
    float* patch_logits = logits + (size_t)B * 2;   // [N, 2]

    cudaFuncSetAttribute(gemm_fused_kernel,
                         cudaFuncAttributeMaxDynamicSharedMemorySize,
                         SMEM_BYTES);

    // 1) prep: W1 -> tf32 scratch; patch_logits = b2 broadcast
    cvt_w1_kernel<<<(D_DIM * H_DIM / 4) / 256, 256>>>(W1);
    init_patch_kernel<<<(N * 2 + 255) / 256, 256>>>(b2, patch_logits, N * 2);

    // 2) fused pipelined GEMM (occ 2: 4 warps/SMSP for latency hiding)
    dim3 grid(H_DIM / BN, N / BM);
    gemm_fused_kernel<<<grid, THREADS, SMEM_BYTES>>>(features, attention, b1,
                                                     W2, patch_logits);

    // 3) ragged per-bag segment sum
    bag_sum_kernel<<<B, 256>>>(patch_logits, bag_sizes, logits);
}